// round 2
// baseline (speedup 1.0000x reference)
#include <cuda_runtime.h>
#include <math.h>

#define HIDDEN 128
#define NF 128
#define NG 50
#define EB 4
#define MAXN 40000
#define LN2f 0.69314718055994530942f

typedef unsigned long long u64;

// ---------- packed f32x2 helpers (Blackwell FFMA2 path) ----------
__device__ __forceinline__ u64 pack2(float lo, float hi) {
    u64 r; asm("mov.b64 %0,{%1,%2};" : "=l"(r) : "f"(lo), "f"(hi)); return r;
}
__device__ __forceinline__ u64 dup2(float a) {
    u64 r; asm("mov.b64 %0,{%1,%1};" : "=l"(r) : "f"(a)); return r;
}
__device__ __forceinline__ void unpack2(u64 v, float& lo, float& hi) {
    asm("mov.b64 {%0,%1},%2;" : "=f"(lo), "=f"(hi) : "l"(v));
}
__device__ __forceinline__ void fma2(u64& d, u64 a, u64 b) {
    asm("fma.rn.f32x2 %0,%1,%2,%0;" : "+l"(d) : "l"(a), "l"(b));
}
// vector fp32 atomic reduction (PTX ISA 8.1+, sm_90+)
__device__ __forceinline__ void red_add_v4(float* p, float a, float b, float c, float d) {
    asm volatile("red.global.add.v4.f32 [%0], {%1,%2,%3,%4};"
                 :: "l"(p), "f"(a), "f"(b), "f"(c), "f"(d) : "memory");
}

__device__ __forceinline__ float sspf(float x) {
    // shifted softplus: log(1+e^x) - log2, numerically stable
    return fmaxf(x, 0.f) + log1pf(__expf(-fabsf(x))) - LN2f;
}

// ---------- scratch (no allocations allowed) ----------
__device__ float g_h[(size_t)MAXN * NF];
__device__ float g_agg[(size_t)MAXN * NF];
__device__ float g_u[(size_t)MAXN * HIDDEN];

// =================================================================
// Generic row GEMM: Y[n,:] = act( X[n,:] @ W^T + b ), K = F = 128
// W row-major [128][128]; one warp per row, lane owns f = 4l..4l+3
// =================================================================
#define ROW_SMEM ((128 * 128 + 128) * 4)

__global__ __launch_bounds__(256)
void row_gemm_kernel(const float* __restrict__ X, const float* __restrict__ W,
                     const float* __restrict__ B, float* __restrict__ Y,
                     int N, int doSsp) {
    extern __shared__ float sm[];
    float* sWT = sm;            // [j][f] = W[f][j]
    float* sB  = sm + 128 * 128;

    int tid = threadIdx.x;
    for (int i = tid; i < 128 * 128; i += blockDim.x) {
        int f = i >> 7, j = i & 127;
        sWT[j * 128 + f] = W[i];
    }
    if (tid < 128) sB[tid] = B ? B[tid] : 0.f;
    __syncthreads();

    int lane = tid & 31, warp = tid >> 5;
    int gw = blockIdx.x * (blockDim.x >> 5) + warp;
    int tw = gridDim.x * (blockDim.x >> 5);
    float4 bv = ((const float4*)sB)[lane];

    for (int n = gw; n < N; n += tw) {
        float4 xv = *(const float4*)(X + (size_t)n * 128 + 4 * lane);
        u64 acc0 = pack2(bv.x, bv.y);
        u64 acc1 = pack2(bv.z, bv.w);
        #pragma unroll 4
        for (int s = 0; s < 32; s++) {
            float x0 = __shfl_sync(0xffffffffu, xv.x, s);
            float x1 = __shfl_sync(0xffffffffu, xv.y, s);
            float x2 = __shfl_sync(0xffffffffu, xv.z, s);
            float x3 = __shfl_sync(0xffffffffu, xv.w, s);
            const float* wp = sWT + (s * 4) * 128;
            ulonglong2 r0 = ((const ulonglong2*)(wp      ))[lane];
            ulonglong2 r1 = ((const ulonglong2*)(wp + 128))[lane];
            ulonglong2 r2 = ((const ulonglong2*)(wp + 256))[lane];
            ulonglong2 r3 = ((const ulonglong2*)(wp + 384))[lane];
            u64 a;
            a = dup2(x0); fma2(acc0, a, r0.x); fma2(acc1, a, r0.y);
            a = dup2(x1); fma2(acc0, a, r1.x); fma2(acc1, a, r1.y);
            a = dup2(x2); fma2(acc0, a, r2.x); fma2(acc1, a, r2.y);
            a = dup2(x3); fma2(acc0, a, r3.x); fma2(acc1, a, r3.y);
        }
        float o0, o1, o2, o3;
        unpack2(acc0, o0, o1); unpack2(acc1, o2, o3);
        if (doSsp) { o0 = sspf(o0); o1 = sspf(o1); o2 = sspf(o2); o3 = sspf(o3); }
        *(float4*)(Y + (size_t)n * 128 + 4 * lane) = make_float4(o0, o1, o2, o3);
    }
}

// =================================================================
// Fused edge kernel: per edge
//   t = ssp(attr @ w1^T + b1)           (50 -> 128)
//   Wf = (t @ w2^T + b2) * C(edge_w)    (128 -> 128)
//   msg = h[src] * Wf ; atomic agg[dst] += msg
// One warp handles EB=4 edges; lane owns filters f = 4l..4l+3.
// =================================================================
#define EDGE_SMEM ((NG * NF + NF * NF + NF + NF + 8 * EB * NF) * 4)

__global__ __launch_bounds__(256, 2)
void edge_kernel(const float* __restrict__ h, const int* __restrict__ ei,
                 const float* __restrict__ ew, const float* __restrict__ attr,
                 const float* __restrict__ w1, const float* __restrict__ b1,
                 const float* __restrict__ w2, const float* __restrict__ b2,
                 float* __restrict__ agg, int E) {
    extern __shared__ float sm[];
    float* sW1 = sm;                       // [k][f], 50*128
    float* sW2 = sW1 + NG * NF;            // [j][f], 128*128
    float* sB1 = sW2 + NF * NF;            // 128
    float* sB2 = sB1 + NF;                 // 128
    float* sT  = sB2 + NF;                 // [warp][EB][128]

    int tid = threadIdx.x;
    for (int i = tid; i < NG * NF; i += 256) {
        int f = i / NG, k = i - f * NG;
        sW1[k * NF + f] = w1[i];
    }
    for (int i = tid; i < NF * NF; i += 256) {
        int f = i >> 7, j = i & 127;
        sW2[j * NF + f] = w2[i];
    }
    if (tid < NF) { sB1[tid] = b1[tid]; sB2[tid] = b2[tid]; }
    __syncthreads();

    int lane = tid & 31, warp = tid >> 5;
    float4 b1v = ((const float4*)sB1)[lane];
    float4 b2v = ((const float4*)sB2)[lane];
    u64 b1lo = pack2(b1v.x, b1v.y), b1hi = pack2(b1v.z, b1v.w);
    u64 b2lo = pack2(b2v.x, b2v.y), b2hi = pack2(b2v.z, b2v.w);
    float* myT = sT + (warp * EB) * NF;

    int ngroups = (E + EB - 1) / EB;
    int gw = blockIdx.x * 8 + warp;
    int tw = gridDim.x * 8;

    for (int g = gw; g < ngroups; g += tw) {
        int ebase = g * EB;
        float a0[EB], a1[EB], cv[EB];
        int srcv[EB], dstv[EB];
        #pragma unroll
        for (int e = 0; e < EB; e++) {
            int idx = ebase + e;
            bool valid = idx < E;
            int ii = valid ? idx : (E - 1);
            a0[e] = (lane < NG)      ? attr[(size_t)ii * NG + lane]      : 0.f;
            a1[e] = (lane + 32 < NG) ? attr[(size_t)ii * NG + lane + 32] : 0.f;
            srcv[e] = ei[ii];
            dstv[e] = ei[E + ii];
            float w = ew[ii];
            cv[e] = valid ? 0.5f * (cospif(w * 0.1f) + 1.0f) : 0.f;
        }

        // ---- stage 1: t = attr @ w1^T + b1 ----
        u64 T0[EB], T1[EB];
        #pragma unroll
        for (int e = 0; e < EB; e++) { T0[e] = b1lo; T1[e] = b1hi; }
        #pragma unroll 2
        for (int k = 0; k < NG; k++) {
            ulonglong2 wv = ((const ulonglong2*)(sW1 + k * NF))[lane];
            #pragma unroll
            for (int e = 0; e < EB; e++) {
                float av = (k < 32) ? a0[e] : a1[e];
                float a = __shfl_sync(0xffffffffu, av, k & 31);
                u64 aa = dup2(a);
                fma2(T0[e], aa, wv.x);
                fma2(T1[e], aa, wv.y);
            }
        }
        // ssp + stage into smem for stage-2 broadcast
        __syncwarp();
        #pragma unroll
        for (int e = 0; e < EB; e++) {
            float t0, t1, t2, t3;
            unpack2(T0[e], t0, t1); unpack2(T1[e], t2, t3);
            t0 = sspf(t0); t1 = sspf(t1); t2 = sspf(t2); t3 = sspf(t3);
            *(float4*)(myT + e * NF + 4 * lane) = make_float4(t0, t1, t2, t3);
        }
        __syncwarp();

        // ---- stage 2: Wf = t @ w2^T + b2 ----
        u64 U0[EB], U1[EB];
        #pragma unroll
        for (int e = 0; e < EB; e++) { U0[e] = b2lo; U1[e] = b2hi; }
        for (int s = 0; s < 32; s++) {
            const float* wp = sW2 + (s * 4) * NF;
            ulonglong2 r0 = ((const ulonglong2*)(wp      ))[lane];
            ulonglong2 r1 = ((const ulonglong2*)(wp + 128))[lane];
            ulonglong2 r2 = ((const ulonglong2*)(wp + 256))[lane];
            ulonglong2 r3 = ((const ulonglong2*)(wp + 384))[lane];
            #pragma unroll
            for (int e = 0; e < EB; e++) {
                float4 tv = *(const float4*)(myT + e * NF + 4 * s);  // broadcast
                u64 a;
                a = dup2(tv.x); fma2(U0[e], a, r0.x); fma2(U1[e], a, r0.y);
                a = dup2(tv.y); fma2(U0[e], a, r1.x); fma2(U1[e], a, r1.y);
                a = dup2(tv.z); fma2(U0[e], a, r2.x); fma2(U1[e], a, r2.y);
                a = dup2(tv.w); fma2(U0[e], a, r3.x); fma2(U1[e], a, r3.y);
            }
        }

        // ---- epilogue: envelope * gather * scatter-add ----
        #pragma unroll
        for (int e = 0; e < EB; e++) {
            float W0, W1, W2, W3;
            unpack2(U0[e], W0, W1); unpack2(U1[e], W2, W3);
            float c = cv[e];
            float4 hv = *(const float4*)(h + (size_t)srcv[e] * NF + 4 * lane);
            float m0 = hv.x * W0 * c;
            float m1 = hv.y * W1 * c;
            float m2 = hv.z * W2 * c;
            float m3 = hv.w * W3 * c;
            red_add_v4(agg + (size_t)dstv[e] * NF + 4 * lane, m0, m1, m2, m3);
        }
        __syncwarp();
    }
}

// =================================================================
extern "C" void kernel_launch(void* const* d_in, const int* in_sizes, int n_in,
                              void* d_out, int out_size) {
    const float* x    = (const float*)d_in[0];
    const int*   ei   = (const int*)  d_in[1];
    const float* ew   = (const float*)d_in[2];
    const float* attr = (const float*)d_in[3];
    const float* w1   = (const float*)d_in[4];
    const float* b1   = (const float*)d_in[5];
    const float* w2   = (const float*)d_in[6];
    const float* b2   = (const float*)d_in[7];
    const float* l1w  = (const float*)d_in[8];
    const float* l2w  = (const float*)d_in[9];
    const float* l2b  = (const float*)d_in[10];
    const float* lw   = (const float*)d_in[11];
    const float* lb   = (const float*)d_in[12];
    float* out = (float*)d_out;

    int N = in_sizes[0] / HIDDEN;
    int E = in_sizes[2];

    void *ph = nullptr, *pagg = nullptr, *pu = nullptr;
    cudaGetSymbolAddress(&ph,   g_h);
    cudaGetSymbolAddress(&pagg, g_agg);
    cudaGetSymbolAddress(&pu,   g_u);

    cudaFuncSetAttribute(row_gemm_kernel, cudaFuncAttributeMaxDynamicSharedMemorySize, ROW_SMEM);
    cudaFuncSetAttribute(edge_kernel,     cudaFuncAttributeMaxDynamicSharedMemorySize, EDGE_SMEM);

    // agg = 0
    cudaMemsetAsync(pagg, 0, (size_t)N * NF * sizeof(float));
    // h = x @ lin1_w^T
    row_gemm_kernel<<<444, 256, ROW_SMEM>>>(x, l1w, nullptr, (float*)ph, N, 0);
    // fused edge filter MLP + CFConv message + scatter
    edge_kernel<<<296, 256, EDGE_SMEM>>>((const float*)ph, ei, ew, attr,
                                         w1, b1, w2, b2, (float*)pagg, E);
    // u = ssp(agg @ lin2_w^T + lin2_b)
    row_gemm_kernel<<<444, 256, ROW_SMEM>>>((const float*)pagg, l2w, l2b, (float*)pu, N, 1);
    // out = u @ lin_w^T + lin_b
    row_gemm_kernel<<<444, 256, ROW_SMEM>>>((const float*)pu, lw, lb, out, N, 0);
}